// round 1
// baseline (speedup 1.0000x reference)
#include <cuda_runtime.h>
#include <math.h>

// ---------------- constants ----------------
#define BATCH   1024
#define NT      10       // tokens = attn qubits
#define PADDED  30
#define DEPTH   4
#define LAYERS  2
#define NHEADS  2
#define NCLS    10

// g_mats layout (each matrix = 4 float2, row-major 2x2):
//   stem   : [0,120)    index (t*4+l)*3+w
//   attn   : [120,600)  index (((lay*2+h)*3+g)*4+l)*10+w
//   ffn    : [600,840)  index ((lay*10+t)*4+l)*3+w
//   reduce : [840,960)  index (t*4+l)*3+w
__device__ float2         g_mats[960 * 4];
__device__ unsigned short g_perm[DEPTH][1024];   // inverse permutation of CNOT ring, r=l+1
__device__ float          g_H[BATCH * PADDED];
__device__ float          g_attn[BATCH * PADDED * NHEADS];

// ---------------- helpers ----------------
__device__ __forceinline__ float2 cmul(float2 a, float2 b) {
    return make_float2(a.x * b.x - a.y * b.y, a.x * b.y + a.y * b.x);
}
__device__ __forceinline__ float2 cadd(float2 a, float2 b) {
    return make_float2(a.x + b.x, a.y + b.y);
}

// 3-qubit circuit, fully in registers. M points at 12 consecutive matrices
// (layer-major: (l*3+w)). Computes <Z_0..2>.
__device__ __forceinline__ void run3(float x0, float x1, float x2,
                                     const float2* __restrict__ M, float E[3]) {
    float c[3], s[3];
    sincosf(0.5f * x0, &s[0], &c[0]);
    sincosf(0.5f * x1, &s[1], &c[1]);
    sincosf(0.5f * x2, &s[2], &c[2]);
    float2 a[8];
#pragma unroll
    for (int i = 0; i < 8; i++) {
        float v = ((i >> 2) & 1 ? s[0] : c[0]) *
                  ((i >> 1) & 1 ? s[1] : c[1]) *
                  ((i      ) & 1 ? s[2] : c[2]);
        a[i] = make_float2(v, 0.f);
    }
#pragma unroll
    for (int l = 0; l < 4; l++) {
#pragma unroll
        for (int w = 0; w < 3; w++) {
            const float2* m = M + (l * 3 + w) * 4;
            const int p = 2 - w;
#pragma unroll
            for (int i0 = 0; i0 < 8; i0++) {
                if (i0 & (1 << p)) continue;
                int i1 = i0 | (1 << p);
                float2 A = a[i0], B = a[i1];
                a[i0] = cadd(cmul(m[0], A), cmul(m[1], B));
                a[i1] = cadd(cmul(m[2], A), cmul(m[3], B));
            }
        }
        const int r = (l & 1) + 1;  // (l % (n-1)) + 1 with n=3
#pragma unroll
        for (int i = 0; i < 3; i++) {
            int pc = 2 - i;
            int pt = 2 - ((i + r) % 3);
#pragma unroll
            for (int idx = 0; idx < 8; idx++) {
                if (((idx >> pc) & 1) && !((idx >> pt) & 1)) {
                    int j = idx | (1 << pt);
                    float2 t = a[idx]; a[idx] = a[j]; a[j] = t;
                }
            }
        }
    }
    E[0] = E[1] = E[2] = 0.f;
#pragma unroll
    for (int i = 0; i < 8; i++) {
        float p = a[i].x * a[i].x + a[i].y * a[i].y;
        E[0] += (i & 4) ? -p : p;
        E[1] += (i & 2) ? -p : p;
        E[2] += (i & 1) ? -p : p;
    }
}

// ---------------- prep: rot matrices + permutation tables ----------------
__global__ void prep_kernel(const float* __restrict__ t_stem,
                            const float* __restrict__ t_attn,
                            const float* __restrict__ t_ffn,
                            const float* __restrict__ t_red) {
    int i = blockIdx.x * blockDim.x + threadIdx.x;
    if (i < 960) {
        const float* a;
        if (i < 120)      a = t_stem + i * 3;
        else if (i < 600) a = t_attn + (i - 120) * 3;
        else if (i < 840) a = t_ffn  + (i - 600) * 3;
        else              a = t_red  + (i - 840) * 3;
        float phi = a[0], th = a[1], om = a[2];
        float c, s, cp, sp, cm, sm;
        sincosf(0.5f * th, &s, &c);
        sincosf(0.5f * (phi + om), &sp, &cp);
        sincosf(0.5f * (phi - om), &sm, &cm);
        float2* m = &g_mats[i * 4];
        m[0] = make_float2( cp * c, -sp * c);
        m[1] = make_float2(-cm * s, -sm * s);
        m[2] = make_float2( cm * s, -sm * s);
        m[3] = make_float2( cp * c,  sp * c);
    } else if (i < 960 + 4 * 1024) {
        int p = i - 960;
        int l = p >> 10;
        int x = p & 1023;
        int r = l + 1;          // (l % 9) + 1 for l<4
        int y = x;
#pragma unroll
        for (int q = 0; q < 10; q++)
            if ((y >> (9 - q)) & 1) y ^= 1 << (9 - ((q + r) % 10));
        g_perm[l][y] = (unsigned short)x;   // perm[y] = F^{-1}(y)
    }
}

// ---------------- stem ----------------
__global__ void stem_kernel(const float* __restrict__ x) {
    int i = blockIdx.x * blockDim.x + threadIdx.x;   // t*1024 + b
    int t = i >> 10, b = i & 1023;
    float E[3];
    run3(x[b * 30 + 3 * t], x[b * 30 + 3 * t + 1], x[b * 30 + 3 * t + 2],
         g_mats + (t * 12) * 4, E);
#pragma unroll
    for (int k = 0; k < 3; k++) g_H[b * 30 + 3 * t + k] = E[k];
}

// ---------------- attention: 10-qubit circuit, one block per instance ----------------
__global__ void __launch_bounds__(512) attn_kernel(int lay) {
    __shared__ float2 st[1024];
    __shared__ float2 mats[160];           // 40 gates x 4
    __shared__ float cw[10], sw[10], acc[10];

    const int inst = blockIdx.x;
    const int b  = inst & 1023;
    const int hg = inst >> 10;             // [0,6)
    const int h  = hg / 3, g = hg % 3;
    const int tid = threadIdx.x;

    // gate matrices for this circuit
    const int circ = ((lay * 2 + h) * 3 + g);
    const float2* gm = g_mats + (120 + circ * 40) * 4;
    if (tid < 160) mats[tid] = gm[tid];
    if (tid < 10) {
        float ang = g_H[b * 30 + 3 * tid + g];
        sincosf(0.5f * ang, &sw[tid], &cw[tid]);
        acc[tid] = 0.f;
    }
    __syncthreads();

    // product-state init (= RY embedding applied to |0..0>)
#pragma unroll
    for (int half = 0; half < 2; half++) {
        int k = tid + half * 512;
        float v = 1.f;
#pragma unroll
        for (int w = 0; w < 10; w++)
            v *= ((k >> (9 - w)) & 1) ? sw[w] : cw[w];
        st[k] = make_float2(v, 0.f);
    }
    __syncthreads();

#pragma unroll
    for (int l = 0; l < 4; l++) {
#pragma unroll
        for (int w = 0; w < 10; w++) {
            const int p = 9 - w;
            int j = tid;
            int i0 = ((j >> p) << (p + 1)) | (j & ((1 << p) - 1));
            int i1 = i0 | (1 << p);
            float2 A = st[i0], B = st[i1];
            const float2* m = &mats[(l * 10 + w) * 4];
            st[i0] = cadd(cmul(m[0], A), cmul(m[1], B));
            st[i1] = cadd(cmul(m[2], A), cmul(m[3], B));
            __syncthreads();
        }
        // CNOT ring as a single permutation gather
        int p0 = g_perm[l][tid];
        int p1 = g_perm[l][tid + 512];
        float2 v0 = st[p0], v1 = st[p1];
        __syncthreads();
        st[tid] = v0; st[tid + 512] = v1;
        __syncthreads();
    }

    // <Z_w> for w=0..9
    float local[10];
#pragma unroll
    for (int w = 0; w < 10; w++) local[w] = 0.f;
#pragma unroll
    for (int half = 0; half < 2; half++) {
        int k = tid + half * 512;
        float2 a = st[k];
        float pr = a.x * a.x + a.y * a.y;
#pragma unroll
        for (int w = 0; w < 10; w++)
            local[w] += ((k >> (9 - w)) & 1) ? -pr : pr;
    }
#pragma unroll
    for (int w = 0; w < 10; w++) {
        float v = local[w];
#pragma unroll
        for (int off = 16; off; off >>= 1)
            v += __shfl_down_sync(0xffffffffu, v, off);
        if ((tid & 31) == 0) atomicAdd(&acc[w], v);
    }
    __syncthreads();
    if (tid < 10)
        g_attn[b * 60 + h * 30 + 3 * tid + g] = acc[tid];
}

// ---------------- W_O projection + residual ----------------
__global__ void wo_kernel(const float* __restrict__ W_O, int lay) {
    int i = blockIdx.x * blockDim.x + threadIdx.x;  // b*30 + j
    int b = i / 30, j = i % 30;
    const float* w = W_O + (lay * 30 + j) * 60;
    const float* a = g_attn + b * 60;
    float s = 0.f;
#pragma unroll
    for (int k = 0; k < 60; k++) s += a[k] * w[k];
    g_H[i] += s;
}

// ---------------- FFN (warp per batch element, shuffled residual) ----------------
__global__ void ffn_kernel(int lay) {
    int gt = blockIdx.x * blockDim.x + threadIdx.x;
    int b = gt >> 5, lane = gt & 31;
    float in[3] = {0.f, 0.f, 0.f};
    if (lane < 10) {
#pragma unroll
        for (int j = 0; j < 3; j++) {
            int f = 3 * lane + j;
            in[j] = g_H[b * 30 + 3 * (f % 10) + (f / 10)];
        }
    }
    __syncwarp();
    if (lane < 10) {
        float E[3];
        run3(in[0], in[1], in[2], g_mats + (600 + (lay * 10 + lane) * 12) * 4, E);
#pragma unroll
        for (int j = 0; j < 3; j++) g_H[b * 30 + 3 * lane + j] += E[j];
    }
}

// ---------------- reduce + classification head ----------------
__global__ void reduce_cls_kernel(const float* __restrict__ Wc,
                                  const float* __restrict__ bc,
                                  float* __restrict__ out) {
    int gt = blockIdx.x * blockDim.x + threadIdx.x;
    int b = gt >> 5, lane = gt & 31;
    float red = 0.f;
    if (lane < 10) {
        float E[3];
        run3(g_H[b * 30 + 3 * lane], g_H[b * 30 + 3 * lane + 1], g_H[b * 30 + 3 * lane + 2],
             g_mats + (840 + lane * 12) * 4, E);
        red = E[0];
    }
    float rv[10];
#pragma unroll
    for (int t = 0; t < 10; t++)
        rv[t] = __shfl_sync(0xffffffffu, red, t);
    if (lane < 10) {
        float s = bc[lane];
#pragma unroll
        for (int t = 0; t < 10; t++) s += rv[t] * Wc[lane * 10 + t];
        out[b * 10 + lane] = s;
    }
}

// ---------------- launch ----------------
extern "C" void kernel_launch(void* const* d_in, const int* in_sizes, int n_in,
                              void* d_out, int out_size) {
    const float* x_      = (const float*)d_in[0];
    const float* t_stem  = (const float*)d_in[1];
    const float* t_attn  = (const float*)d_in[2];
    const float* W_O     = (const float*)d_in[3];
    const float* t_ffn   = (const float*)d_in[4];
    const float* t_red   = (const float*)d_in[5];
    const float* W_cls   = (const float*)d_in[6];
    const float* b_cls   = (const float*)d_in[7];
    float* out = (float*)d_out;

    prep_kernel<<<20, 256>>>(t_stem, t_attn, t_ffn, t_red);   // 5056 work items
    stem_kernel<<<40, 256>>>(x_);                              // 10240 threads
    for (int l = 0; l < LAYERS; l++) {
        attn_kernel<<<6144, 512>>>(l);
        wo_kernel<<<120, 256>>>(W_O, l);
        ffn_kernel<<<128, 256>>>(l);
    }
    reduce_cls_kernel<<<128, 256>>>(W_cls, b_cls, out);
}

// round 3
// speedup vs baseline: 2.3543x; 2.3543x over previous
#include <cuda_runtime.h>
#include <math.h>

#define BATCH   1024
#define NT      10
#define PADDED  30
#define DEPTH   4
#define LAYERS  2
#define NHEADS  2
#define NCLS    10

typedef unsigned long long u64;

// g_mats layout (each matrix = 4 float2, row-major 2x2):
//   stem   : [0,120)    (t*4+l)*3+w
//   attn   : [120,600)  (((lay*2+h)*3+g)*4+l)*10+w
//   ffn    : [600,840)  ((lay*10+t)*4+l)*3+w
//   reduce : [840,960)  (t*4+l)*3+w
__device__ float2 g_mats[960 * 4];
__device__ float  g_H[BATCH * PADDED];
__device__ float  g_attn[BATCH * PADDED * NHEADS];

// ================= compile-time GF(2) mask tables =================
__host__ __device__ constexpr int parity(unsigned x) {
    int p = 0; while (x) { p ^= (int)(x & 1u); x >>= 1; } return p;
}

struct Masks {
    unsigned pm[DEPTH][NT];  // pair mask  m = column w of L_C^{-1}
    unsigned am[DEPTH][NT];  // parity mask a = row w of L_C
    unsigned zm[NT];         // measurement mask = row w of L_total
};

__host__ __device__ constexpr Masks make_masks() {
    Masks M{};
    for (int l = 0; l < DEPTH; l++) {
        unsigned R[NT]{}, Ri[NT]{};
        for (int u = 0; u < NT; u++) { R[u] = 1u << u; Ri[u] = 1u << u; }
        // L_C = layers 0..l-1 applied in order (sequential CNOT ring, r=ll+1)
        for (int ll = 0; ll < l; ll++) {
            int r = ll + 1;
            for (int i = 0; i < NT; i++) R[(i + r) % NT] ^= R[i];
        }
        // L_C^{-1}: inverse ops in reverse order
        for (int ll = l - 1; ll >= 0; ll--) {
            int r = ll + 1;
            for (int i = NT - 1; i >= 0; i--) Ri[(i + r) % NT] ^= Ri[i];
        }
        for (int w = 0; w < NT; w++) {
            unsigned m = 0;
            for (int u = 0; u < NT; u++) if ((Ri[u] >> w) & 1u) m |= 1u << u;
            M.pm[l][w] = m;
            M.am[l][w] = R[w];
        }
    }
    unsigned R[NT]{};
    for (int u = 0; u < NT; u++) R[u] = 1u << u;
    for (int ll = 0; ll < DEPTH; ll++) {
        int r = ll + 1;
        for (int i = 0; i < NT; i++) R[(i + r) % NT] ^= R[i];
    }
    for (int w = 0; w < NT; w++) M.zm[w] = R[w];
    return M;
}
constexpr Masks MK = make_masks();

// ================= packed f32x2 complex helpers =================
__device__ __forceinline__ u64 pack2(float lo, float hi) {
    u64 r; asm("mov.b64 %0, {%1,%2};" : "=l"(r) : "f"(lo), "f"(hi)); return r;
}
__device__ __forceinline__ float2 unpack2(u64 a) {
    float2 f; asm("mov.b64 {%0,%1}, %2;" : "=f"(f.x), "=f"(f.y) : "l"(a)); return f;
}
__device__ __forceinline__ u64 swap2(u64 a) {
    u64 r; asm("{ .reg .b32 lo, hi; mov.b64 {lo,hi}, %1; mov.b64 %0, {hi,lo}; }" : "=l"(r) : "l"(a)); return r;
}
__device__ __forceinline__ u64 f2fma(u64 a, u64 b, u64 c) {
    u64 r; asm("fma.rn.f32x2 %0, %1, %2, %3;" : "=l"(r) : "l"(a), "l"(b), "l"(c)); return r;
}
__device__ __forceinline__ u64 f2mul(u64 a, u64 b) {
    u64 r; asm("mul.rn.f32x2 %0, %1, %2;" : "=l"(r) : "l"(a), "l"(b)); return r;
}
__device__ __forceinline__ u64 shfl64_xor(u64 v, int m) {
    unsigned lo = (unsigned)v, hi = (unsigned)(v >> 32);
    lo = __shfl_xor_sync(0xffffffffu, lo, m);
    hi = __shfl_xor_sync(0xffffffffu, hi, m);
    return ((u64)hi << 32) | lo;
}

// out = own_coef * A + oth_coef * B  (complex; coefs given as xx=(cx,cx), yy=(-cy,cy))
__device__ __forceinline__ u64 cmix(u64 A, u64 As, u64 B, u64 Bs,
                                    u64 oxx, u64 oyy, u64 txx, u64 tyy) {
    return f2fma(oxx, A, f2fma(oyy, As, f2fma(txx, B, f2mul(tyy, Bs))));
}

// ================= gate application (all indices compile-time) =================
// pure-local butterfly (pair mask entirely within lane-local bits)
template<unsigned MLO, unsigned ALO, int J>
__device__ __forceinline__ void local_loop(u64* st, u64 oxx, u64 tyy,
                                           u64 oyy0, u64 oyy1, u64 txx0, u64 txx1) {
    if constexpr (J < 32) {
        constexpr unsigned LOW = MLO & (0u - MLO);
        if constexpr ((J & (int)LOW) == 0) {
            constexpr int J2 = J ^ (int)MLO;
            constexpr int P  = parity(ALO & (unsigned)J);
            constexpr int P2 = parity(ALO & (unsigned)J2);
            u64 A = st[J], B = st[J2];
            u64 As = swap2(A), Bs = swap2(B);
            st[J]  = cmix(A, As, B, Bs, oxx, P  ? oyy1 : oyy0, P  ? txx1 : txx0, tyy);
            st[J2] = cmix(B, Bs, A, As, oxx, P2 ? oyy1 : oyy0, P2 ? txx1 : txx0, tyy);
        }
        local_loop<MLO, ALO, J + 1>(st, oxx, tyy, oyy0, oyy1, txx0, txx1);
    }
}

// pure-lane butterfly (pair mask entirely within lane bits)
template<unsigned MHI, unsigned ALO, int J>
__device__ __forceinline__ void lane_loop(u64* st, u64 oxx, u64 tyy,
                                          u64 oyy0, u64 oyy1, u64 txx0, u64 txx1) {
    if constexpr (J < 32) {
        constexpr int P = parity(ALO & (unsigned)J);
        u64 A = st[J];
        u64 B = shfl64_xor(A, (int)MHI);
        u64 As = swap2(A), Bs = swap2(B);
        st[J] = cmix(A, As, B, Bs, oxx, P ? oyy1 : oyy0, P ? txx1 : txx0, tyy);
        lane_loop<MHI, ALO, J + 1>(st, oxx, tyy, oyy0, oyy1, txx0, txx1);
    }
}

// mixed: pair mask spans lane and local bits
template<unsigned MLO, unsigned MHI, unsigned ALO, int J>
__device__ __forceinline__ void mixed_loop(u64* st, u64 oxx, u64 tyy,
                                           u64 oyy0, u64 oyy1, u64 txx0, u64 txx1) {
    if constexpr (J < 32) {
        constexpr unsigned LOW = MLO & (0u - MLO);
        if constexpr ((J & (int)LOW) == 0) {
            constexpr int J2 = J ^ (int)MLO;
            constexpr int P  = parity(ALO & (unsigned)J);
            constexpr int P2 = parity(ALO & (unsigned)J2);
            u64 A = st[J], B = st[J2];
            u64 pA = shfl64_xor(B, (int)MHI);   // partner's st[J2] -> pairs with my st[J]
            u64 pB = shfl64_xor(A, (int)MHI);   // partner's st[J]  -> pairs with my st[J2]
            u64 As = swap2(A), Bs = swap2(B), pAs = swap2(pA), pBs = swap2(pB);
            st[J]  = cmix(A, As, pA, pAs, oxx, P  ? oyy1 : oyy0, P  ? txx1 : txx0, tyy);
            st[J2] = cmix(B, Bs, pB, pBs, oxx, P2 ? oyy1 : oyy0, P2 ? txx1 : txx0, tyy);
        }
        mixed_loop<MLO, MHI, ALO, J + 1>(st, oxx, tyy, oyy0, oyy1, txx0, txx1);
    }
}

template<int L, int W>
__device__ __forceinline__ void apply_gate(u64* st, const float2* __restrict__ gm, int lane) {
    constexpr unsigned m   = MK.pm[L][W];
    constexpr unsigned a   = MK.am[L][W];
    constexpr unsigned mlo = m & 31u, mhi = (m >> 5) & 31u;
    constexpr unsigned alo = a & 31u, ahi = (a >> 5) & 31u;
    // SU(2): g11 = conj(g00), g10 = -conj(g01) -> only g00,g01 needed
    float2 g00 = gm[(L * 10 + W) * 4 + 0];
    float2 g01 = gm[(L * 10 + W) * 4 + 1];
    u64 oxx = pack2(g00.x, g00.x);
    u64 oyy = pack2(-g00.y, g00.y);
    u64 txx = pack2(g01.x, g01.x);
    u64 tyy = pack2(-g01.y, g01.y);
    constexpr u64 SGN = 0x8000000080000000ull;
    u64 oyyN = oyy ^ SGN;      // parity-1 own coef
    u64 txxN = txx ^ SGN;      // parity-1 other coef
    int plane = (int)(__popc(ahi & (unsigned)lane) & 1);
    u64 oyy0 = plane ? oyyN : oyy;
    u64 oyy1 = plane ? oyy  : oyyN;
    u64 txx0 = plane ? txxN : txx;
    u64 txx1 = plane ? txx  : txxN;
    if constexpr (mhi == 0u) {
        local_loop<mlo, alo, 0>(st, oxx, tyy, oyy0, oyy1, txx0, txx1);
    } else if constexpr (mlo == 0u) {
        lane_loop<mhi, alo, 0>(st, oxx, tyy, oyy0, oyy1, txx0, txx1);
    } else {
        mixed_loop<mlo, mhi, alo, 0>(st, oxx, tyy, oyy0, oyy1, txx0, txx1);
    }
}

template<int G>
__device__ __forceinline__ void run_gates(u64* st, const float2* __restrict__ gm, int lane) {
    if constexpr (G < DEPTH * NT) {
        apply_gate<G / NT, G % NT>(st, gm, lane);
        run_gates<G + 1>(st, gm, lane);
    }
}

// ================= measurement (parity masks) =================
template<unsigned ZLO, int J>
__device__ __forceinline__ void sum_loop(const float* pr, float& acc) {
    if constexpr (J < 32) {
        if constexpr (parity(ZLO & (unsigned)J)) acc -= pr[J]; else acc += pr[J];
        sum_loop<ZLO, J + 1>(pr, acc);
    }
}
template<int W>
__device__ __forceinline__ void meas_from(const float* pr, float* res, int lane) {
    if constexpr (W < NT) {
        constexpr unsigned z = MK.zm[W];
        constexpr unsigned zlo = z & 31u, zhi = (z >> 5) & 31u;
        float acc = 0.f;
        sum_loop<zlo, 0>(pr, acc);
        int sl = (int)(__popc(zhi & (unsigned)lane) & 1);
        res[W] = sl ? -acc : acc;
        meas_from<W + 1>(pr, res, lane);
    }
}

// ================= 3-qubit register circuit =================
__device__ __forceinline__ float2 cmul(float2 a, float2 b) {
    return make_float2(a.x * b.x - a.y * b.y, a.x * b.y + a.y * b.x);
}
__device__ __forceinline__ float2 cadd(float2 a, float2 b) {
    return make_float2(a.x + b.x, a.y + b.y);
}
__device__ __forceinline__ void run3(float x0, float x1, float x2,
                                     const float2* __restrict__ M, float E[3]) {
    float c[3], s[3];
    sincosf(0.5f * x0, &s[0], &c[0]);
    sincosf(0.5f * x1, &s[1], &c[1]);
    sincosf(0.5f * x2, &s[2], &c[2]);
    float2 a[8];
#pragma unroll
    for (int i = 0; i < 8; i++) {
        float v = ((i >> 2) & 1 ? s[0] : c[0]) *
                  ((i >> 1) & 1 ? s[1] : c[1]) *
                  ((i      ) & 1 ? s[2] : c[2]);
        a[i] = make_float2(v, 0.f);
    }
#pragma unroll
    for (int l = 0; l < 4; l++) {
#pragma unroll
        for (int w = 0; w < 3; w++) {
            const float2* m = M + (l * 3 + w) * 4;
            const int p = 2 - w;
#pragma unroll
            for (int i0 = 0; i0 < 8; i0++) {
                if (i0 & (1 << p)) continue;
                int i1 = i0 | (1 << p);
                float2 A = a[i0], B = a[i1];
                a[i0] = cadd(cmul(m[0], A), cmul(m[1], B));
                a[i1] = cadd(cmul(m[2], A), cmul(m[3], B));
            }
        }
        const int r = (l & 1) + 1;
#pragma unroll
        for (int i = 0; i < 3; i++) {
            int pc = 2 - i;
            int pt = 2 - ((i + r) % 3);
#pragma unroll
            for (int idx = 0; idx < 8; idx++) {
                if (((idx >> pc) & 1) && !((idx >> pt) & 1)) {
                    int j = idx | (1 << pt);
                    float2 t = a[idx]; a[idx] = a[j]; a[j] = t;
                }
            }
        }
    }
    E[0] = E[1] = E[2] = 0.f;
#pragma unroll
    for (int i = 0; i < 8; i++) {
        float p = a[i].x * a[i].x + a[i].y * a[i].y;
        E[0] += (i & 4) ? -p : p;
        E[1] += (i & 2) ? -p : p;
        E[2] += (i & 1) ? -p : p;
    }
}

// ================= prep: Rot matrices =================
__global__ void prep_kernel(const float* __restrict__ t_stem,
                            const float* __restrict__ t_attn,
                            const float* __restrict__ t_ffn,
                            const float* __restrict__ t_red) {
    int i = blockIdx.x * blockDim.x + threadIdx.x;
    if (i < 960) {
        const float* a;
        if (i < 120)      a = t_stem + i * 3;
        else if (i < 600) a = t_attn + (i - 120) * 3;
        else if (i < 840) a = t_ffn  + (i - 600) * 3;
        else              a = t_red  + (i - 840) * 3;
        float phi = a[0], th = a[1], om = a[2];
        float c, s, cp, sp, cm, sm;
        sincosf(0.5f * th, &s, &c);
        sincosf(0.5f * (phi + om), &sp, &cp);
        sincosf(0.5f * (phi - om), &sm, &cm);
        float2* m = &g_mats[i * 4];
        m[0] = make_float2( cp * c, -sp * c);
        m[1] = make_float2(-cm * s, -sm * s);
        m[2] = make_float2( cm * s, -sm * s);
        m[3] = make_float2( cp * c,  sp * c);
    }
}

// ================= stem =================
__global__ void stem_kernel(const float* __restrict__ x) {
    int i = blockIdx.x * blockDim.x + threadIdx.x;
    int t = i >> 10, b = i & 1023;
    float E[3];
    run3(x[b * 30 + 3 * t], x[b * 30 + 3 * t + 1], x[b * 30 + 3 * t + 2],
         g_mats + (t * 12) * 4, E);
#pragma unroll
    for (int k = 0; k < 3; k++) g_H[b * 30 + 3 * t + k] = E[k];
}

// ================= attention: warp-resident 10-qubit simulator =================
__global__ void __launch_bounds__(128) attn_kernel(int lay) {
    const int wid  = blockIdx.x * 4 + (threadIdx.x >> 5);   // 0..6143
    const int lane = threadIdx.x & 31;
    const int b  = wid & 1023;
    const int hg = wid >> 10;
    const int h  = hg / 3, g = hg % 3;
    const float2* gm = g_mats + (120 + ((lay * 2 + h) * 3 + g) * 40) * 4;

    // embedding angles -> product state
    float myc = 1.f, mys = 0.f;
    if (lane < NT) {
        float ang = g_H[b * 30 + 3 * lane + g];
        sincosf(0.5f * ang, &mys, &myc);
    }
    float cw[NT], sw[NT];
#pragma unroll
    for (int w = 0; w < NT; w++) {
        cw[w] = __shfl_sync(0xffffffffu, myc, w);
        sw[w] = __shfl_sync(0xffffffffu, mys, w);
    }
    float lf = 1.f;
#pragma unroll
    for (int w = 5; w < NT; w++) lf *= ((lane >> (w - 5)) & 1) ? sw[w] : cw[w];

    u64 st[32];
#pragma unroll
    for (int j = 0; j < 32; j++) {
        float v = lf;
#pragma unroll
        for (int w = 0; w < 5; w++) v *= ((j >> w) & 1) ? sw[w] : cw[w];
        st[j] = pack2(v, 0.f);
    }

    run_gates<0>(st, gm, lane);

    float pr[32];
#pragma unroll
    for (int j = 0; j < 32; j++) {
        float2 f = unpack2(st[j]);
        pr[j] = f.x * f.x + f.y * f.y;
    }
    float res[NT];
    meas_from<0>(pr, res, lane);
#pragma unroll
    for (int w = 0; w < NT; w++) {
#pragma unroll
        for (int off = 16; off; off >>= 1)
            res[w] += __shfl_xor_sync(0xffffffffu, res[w], off);
    }
    if (lane == 0) {
#pragma unroll
        for (int w = 0; w < NT; w++)
            g_attn[b * 60 + h * 30 + 3 * w + g] = res[w];
    }
}

// ================= fused W_O projection + residual + FFN =================
__global__ void wo_ffn_kernel(const float* __restrict__ W_O, int lay) {
    int gt = blockIdx.x * blockDim.x + threadIdx.x;
    int b = gt >> 5, lane = gt & 31;

    float newH = 0.f;
    if (lane < 30) {
        const float* wrow = W_O + (lay * 30 + lane) * 60;
        const float* arow = g_attn + b * 60;
        float s = 0.f;
#pragma unroll
        for (int k = 0; k < 60; k++) s += arow[k] * wrow[k];
        newH = g_H[b * 30 + lane] + s;
    }
    __syncwarp();

    // FFN input shuffle: feature f = 3*lane + j needs H[3*(f%10) + f/10]
    int f0 = 3 * lane, f1 = f0 + 1, f2 = f0 + 2;
    float in0 = __shfl_sync(0xffffffffu, newH, (3 * (f0 % 10) + f0 / 10) & 31);
    float in1 = __shfl_sync(0xffffffffu, newH, (3 * (f1 % 10) + f1 / 10) & 31);
    float in2 = __shfl_sync(0xffffffffu, newH, (3 * (f2 % 10) + f2 / 10) & 31);
    if (lane >= 10) { in0 = 0.f; in1 = 0.f; in2 = 0.f; }
    int t = (lane < 10) ? lane : 0;
    float E[3];
    run3(in0, in1, in2, g_mats + (600 + (lay * 10 + t) * 12) * 4, E);

    float h0 = __shfl_sync(0xffffffffu, newH, (3 * lane) & 31);
    float h1 = __shfl_sync(0xffffffffu, newH, (3 * lane + 1) & 31);
    float h2 = __shfl_sync(0xffffffffu, newH, (3 * lane + 2) & 31);
    if (lane < 10) {
        g_H[b * 30 + 3 * lane + 0] = h0 + E[0];
        g_H[b * 30 + 3 * lane + 1] = h1 + E[1];
        g_H[b * 30 + 3 * lane + 2] = h2 + E[2];
    }
}

// ================= reduce + classification =================
__global__ void reduce_cls_kernel(const float* __restrict__ Wc,
                                  const float* __restrict__ bc,
                                  float* __restrict__ out) {
    int gt = blockIdx.x * blockDim.x + threadIdx.x;
    int b = gt >> 5, lane = gt & 31;
    float red = 0.f;
    if (lane < 10) {
        float E[3];
        run3(g_H[b * 30 + 3 * lane], g_H[b * 30 + 3 * lane + 1], g_H[b * 30 + 3 * lane + 2],
             g_mats + (840 + lane * 12) * 4, E);
        red = E[0];
    }
    float rv[10];
#pragma unroll
    for (int t = 0; t < 10; t++)
        rv[t] = __shfl_sync(0xffffffffu, red, t);
    if (lane < 10) {
        float s = bc[lane];
#pragma unroll
        for (int t = 0; t < 10; t++) s += rv[t] * Wc[lane * 10 + t];
        out[b * 10 + lane] = s;
    }
}

// ================= launch =================
extern "C" void kernel_launch(void* const* d_in, const int* in_sizes, int n_in,
                              void* d_out, int out_size) {
    const float* x_      = (const float*)d_in[0];
    const float* t_stem  = (const float*)d_in[1];
    const float* t_attn  = (const float*)d_in[2];
    const float* W_O     = (const float*)d_in[3];
    const float* t_ffn   = (const float*)d_in[4];
    const float* t_red   = (const float*)d_in[5];
    const float* W_cls   = (const float*)d_in[6];
    const float* b_cls   = (const float*)d_in[7];
    float* out = (float*)d_out;

    prep_kernel<<<4, 256>>>(t_stem, t_attn, t_ffn, t_red);
    stem_kernel<<<40, 256>>>(x_);
    for (int l = 0; l < LAYERS; l++) {
        attn_kernel<<<1536, 128>>>(l);
        wo_ffn_kernel<<<128, 256>>>(W_O, l);
    }
    reduce_cls_kernel<<<128, 256>>>(W_cls, b_cls, out);
}

// round 5
// speedup vs baseline: 2.9987x; 1.2737x over previous
#include <cuda_runtime.h>
#include <math.h>

#define BATCH   1024
#define NT      10
#define PADDED  30
#define DEPTH   4
#define LAYERS  2
#define NHEADS  2
#define NCLS    10

typedef unsigned long long u64;

// g_mats layout (each matrix = 4 float2, row-major 2x2):
//   stem   : [0,120)    (t*4+l)*3+w
//   attn   : [120,600)  (((lay*2+h)*3+g)*4+l)*10+w
//   ffn    : [600,840)  ((lay*10+t)*4+l)*3+w
//   reduce : [840,960)  (t*4+l)*3+w
__device__ float2 g_mats[960 * 4];
__device__ float  g_H[BATCH * PADDED];
__device__ float  g_attn[BATCH * PADDED * NHEADS];

// ================= compile-time GF(2) mask tables =================
__host__ __device__ constexpr int parity(unsigned x) {
    int p = 0; while (x) { p ^= (int)(x & 1u); x >>= 1; } return p;
}

struct Masks {
    unsigned pm[DEPTH][NT];  // pair mask  m = column w of L_l^{-1}
    unsigned am[DEPTH][NT];  // parity mask a = row w of L_l
    unsigned zm[NT];         // measurement mask = row w of L_total
};

__host__ __device__ constexpr Masks make_masks() {
    Masks M{};
    for (int l = 0; l < DEPTH; l++) {
        unsigned R[NT]{}, Ri[NT]{};
        for (int u = 0; u < NT; u++) { R[u] = 1u << u; Ri[u] = 1u << u; }
        for (int ll = 0; ll < l; ll++) {
            int r = ll + 1;
            for (int i = 0; i < NT; i++) R[(i + r) % NT] ^= R[i];
        }
        for (int ll = l - 1; ll >= 0; ll--) {
            int r = ll + 1;
            for (int i = NT - 1; i >= 0; i--) Ri[(i + r) % NT] ^= Ri[i];
        }
        for (int w = 0; w < NT; w++) {
            unsigned m = 0;
            for (int u = 0; u < NT; u++) if ((Ri[u] >> w) & 1u) m |= 1u << u;
            M.pm[l][w] = m;
            M.am[l][w] = R[w];
        }
    }
    unsigned R[NT]{};
    for (int u = 0; u < NT; u++) R[u] = 1u << u;
    for (int ll = 0; ll < DEPTH; ll++) {
        int r = ll + 1;
        for (int i = 0; i < NT; i++) R[(i + r) % NT] ^= R[i];
    }
    for (int w = 0; w < NT; w++) M.zm[w] = R[w];
    return M;
}

// Permuted masks for layers 1..3 (layer 0 is absorbed into the init).
// Search all C(10,5) lane/local assignments; maximize gates whose pair mask
// is fully local (cost 192 vs 320 packed ops).
struct Masks2 {
    unsigned pm[3][NT];
    unsigned am[3][NT];
    unsigned zm[NT];
    int posq[NT];           // position -> qubit
};

__host__ __device__ constexpr Masks2 make_masks2() {
    Masks M = make_masks();
    unsigned bestS = 0x1Fu; int bestScore = -1;
    for (unsigned S = 0; S < 1024u; S++) {
        int pc = 0;
        for (int q = 0; q < NT; q++) pc += (int)((S >> q) & 1u);
        if (pc != 5) continue;
        int score = 0;
        for (int l = 1; l < DEPTH; l++)
            for (int w = 0; w < NT; w++)
                if ((M.pm[l][w] & ~S & 0x3FFu) == 0u) score++;
        if (score > bestScore) { bestScore = score; bestS = S; }
    }
    int qpos[NT]{};
    Masks2 R{};
    {
        int lp = 0, hp = 5;
        for (int q = 0; q < NT; q++) {
            int p = ((bestS >> q) & 1u) ? lp++ : hp++;
            qpos[q] = p;
        }
        for (int q = 0; q < NT; q++) R.posq[qpos[q]] = q;
    }
    for (int l = 1; l < DEPTH; l++)
        for (int w = 0; w < NT; w++) {
            unsigned pm2 = 0, am2 = 0;
            for (int q = 0; q < NT; q++) {
                if ((M.pm[l][w] >> q) & 1u) pm2 |= 1u << qpos[q];
                if ((M.am[l][w] >> q) & 1u) am2 |= 1u << qpos[q];
            }
            R.pm[l - 1][w] = pm2;
            R.am[l - 1][w] = am2;
        }
    for (int w = 0; w < NT; w++) {
        unsigned z2 = 0;
        for (int q = 0; q < NT; q++) if ((M.zm[w] >> q) & 1u) z2 |= 1u << qpos[q];
        R.zm[w] = z2;
    }
    return R;
}
constexpr Masks2 MK2 = make_masks2();

// ================= packed f32x2 complex helpers =================
__device__ __forceinline__ u64 pack2(float lo, float hi) {
    u64 r; asm("mov.b64 %0, {%1,%2};" : "=l"(r) : "f"(lo), "f"(hi)); return r;
}
__device__ __forceinline__ float2 unpack2(u64 a) {
    float2 f; asm("mov.b64 {%0,%1}, %2;" : "=f"(f.x), "=f"(f.y) : "l"(a)); return f;
}
__device__ __forceinline__ u64 swap2(u64 a) {
    u64 r; asm("{ .reg .b32 lo, hi; mov.b64 {lo,hi}, %1; mov.b64 %0, {hi,lo}; }" : "=l"(r) : "l"(a)); return r;
}
__device__ __forceinline__ u64 f2fma(u64 a, u64 b, u64 c) {
    u64 r; asm("fma.rn.f32x2 %0, %1, %2, %3;" : "=l"(r) : "l"(a), "l"(b), "l"(c)); return r;
}
__device__ __forceinline__ u64 f2mul(u64 a, u64 b) {
    u64 r; asm("mul.rn.f32x2 %0, %1, %2;" : "=l"(r) : "l"(a), "l"(b)); return r;
}
__device__ __forceinline__ u64 shfl64_xor(u64 v, int m) {
    unsigned lo = (unsigned)v, hi = (unsigned)(v >> 32);
    lo = __shfl_xor_sync(0xffffffffu, lo, m);
    hi = __shfl_xor_sync(0xffffffffu, hi, m);
    return ((u64)hi << 32) | lo;
}

__device__ __forceinline__ u64 cmix(u64 A, u64 As, u64 B, u64 Bs,
                                    u64 oxx, u64 oyy, u64 txx, u64 tyy) {
    return f2fma(oxx, A, f2fma(oyy, As, f2fma(txx, B, f2mul(tyy, Bs))));
}

__device__ __forceinline__ float2 cmulf(float2 a, float2 b) {
    return make_float2(a.x * b.x - a.y * b.y, a.x * b.y + a.y * b.x);
}

// ================= gate application (all indices compile-time) =================
template<unsigned MLO, unsigned ALO, int J>
__device__ __forceinline__ void local_loop(u64* st, u64 oxx, u64 tyy,
                                           u64 oyy0, u64 oyy1, u64 txx0, u64 txx1) {
    if constexpr (J < 32) {
        constexpr unsigned LOW = MLO & (0u - MLO);
        if constexpr ((J & (int)LOW) == 0) {
            constexpr int J2 = J ^ (int)MLO;
            constexpr int P  = parity(ALO & (unsigned)J);
            constexpr int P2 = parity(ALO & (unsigned)J2);
            u64 A = st[J], B = st[J2];
            u64 As = swap2(A), Bs = swap2(B);
            st[J]  = cmix(A, As, B, Bs, oxx, P  ? oyy1 : oyy0, P  ? txx1 : txx0, tyy);
            st[J2] = cmix(B, Bs, A, As, oxx, P2 ? oyy1 : oyy0, P2 ? txx1 : txx0, tyy);
        }
        local_loop<MLO, ALO, J + 1>(st, oxx, tyy, oyy0, oyy1, txx0, txx1);
    }
}

template<unsigned MHI, unsigned ALO, int J>
__device__ __forceinline__ void lane_loop(u64* st, u64 oxx, u64 tyy,
                                          u64 oyy0, u64 oyy1, u64 txx0, u64 txx1) {
    if constexpr (J < 32) {
        constexpr int P = parity(ALO & (unsigned)J);
        u64 A = st[J];
        u64 B = shfl64_xor(A, (int)MHI);
        u64 As = swap2(A), Bs = swap2(B);
        st[J] = cmix(A, As, B, Bs, oxx, P ? oyy1 : oyy0, P ? txx1 : txx0, tyy);
        lane_loop<MHI, ALO, J + 1>(st, oxx, tyy, oyy0, oyy1, txx0, txx1);
    }
}

template<unsigned MLO, unsigned MHI, unsigned ALO, int J>
__device__ __forceinline__ void mixed_loop(u64* st, u64 oxx, u64 tyy,
                                           u64 oyy0, u64 oyy1, u64 txx0, u64 txx1) {
    if constexpr (J < 32) {
        constexpr unsigned LOW = MLO & (0u - MLO);
        if constexpr ((J & (int)LOW) == 0) {
            constexpr int J2 = J ^ (int)MLO;
            constexpr int P  = parity(ALO & (unsigned)J);
            constexpr int P2 = parity(ALO & (unsigned)J2);
            u64 A = st[J], B = st[J2];
            u64 pA = shfl64_xor(B, (int)MHI);
            u64 pB = shfl64_xor(A, (int)MHI);
            u64 As = swap2(A), Bs = swap2(B), pAs = swap2(pA), pBs = swap2(pB);
            st[J]  = cmix(A, As, pA, pAs, oxx, P  ? oyy1 : oyy0, P  ? txx1 : txx0, tyy);
            st[J2] = cmix(B, Bs, pB, pBs, oxx, P2 ? oyy1 : oyy0, P2 ? txx1 : txx0, tyy);
        }
        mixed_loop<MLO, MHI, ALO, J + 1>(st, oxx, tyy, oyy0, oyy1, txx0, txx1);
    }
}

// L in [0,3) = circuit layers 1..3 (layer 0 absorbed into init)
template<int L, int W>
__device__ __forceinline__ void apply_gate(u64* st, const float2* __restrict__ gm, int lane) {
    constexpr unsigned m   = MK2.pm[L][W];
    constexpr unsigned a   = MK2.am[L][W];
    constexpr unsigned mlo = m & 31u, mhi = (m >> 5) & 31u;
    constexpr unsigned alo = a & 31u, ahi = (a >> 5) & 31u;
    float2 g00 = gm[((L + 1) * 10 + W) * 4 + 0];
    float2 g01 = gm[((L + 1) * 10 + W) * 4 + 1];
    u64 oxx = pack2(g00.x, g00.x);
    u64 oyy = pack2(-g00.y, g00.y);
    u64 txx = pack2(g01.x, g01.x);
    u64 tyy = pack2(-g01.y, g01.y);
    constexpr u64 SGN = 0x8000000080000000ull;
    u64 oyyN = oyy ^ SGN;
    u64 txxN = txx ^ SGN;
    int plane = (int)(__popc(ahi & (unsigned)lane) & 1);
    u64 oyy0 = plane ? oyyN : oyy;
    u64 oyy1 = plane ? oyy  : oyyN;
    u64 txx0 = plane ? txxN : txx;
    u64 txx1 = plane ? txx  : txxN;
    if constexpr (mhi == 0u) {
        local_loop<mlo, alo, 0>(st, oxx, tyy, oyy0, oyy1, txx0, txx1);
    } else if constexpr (mlo == 0u) {
        lane_loop<mhi, alo, 0>(st, oxx, tyy, oyy0, oyy1, txx0, txx1);
    } else {
        mixed_loop<mlo, mhi, alo, 0>(st, oxx, tyy, oyy0, oyy1, txx0, txx1);
    }
}

template<int G>
__device__ __forceinline__ void run_gates(u64* st, const float2* __restrict__ gm, int lane) {
    if constexpr (G < 3 * NT) {
        apply_gate<G / NT, G % NT>(st, gm, lane);
        run_gates<G + 1>(st, gm, lane);
    }
}

// ================= measurement (parity masks) =================
template<unsigned ZLO, int J>
__device__ __forceinline__ void sum_loop(const float* pr, float& acc) {
    if constexpr (J < 32) {
        if constexpr (parity(ZLO & (unsigned)J)) acc -= pr[J]; else acc += pr[J];
        sum_loop<ZLO, J + 1>(pr, acc);
    }
}
template<int W>
__device__ __forceinline__ void meas_from(const float* pr, float* res, int lane) {
    if constexpr (W < NT) {
        constexpr unsigned z = MK2.zm[W];
        constexpr unsigned zlo = z & 31u, zhi = (z >> 5) & 31u;
        float acc = 0.f;
        sum_loop<zlo, 0>(pr, acc);
        int sl = (int)(__popc(zhi & (unsigned)lane) & 1);
        res[W] = sl ? -acc : acc;
        meas_from<W + 1>(pr, res, lane);
    }
}

// compile-time posq gather of embedding factors into position order
template<int P>
__device__ __forceinline__ void gather_factors(float2* fa, float2* fb, float2 va, float2 vb) {
    if constexpr (P < NT) {
        constexpr int q = MK2.posq[P];
        fa[P].x = __shfl_sync(0xffffffffu, va.x, q);
        fa[P].y = __shfl_sync(0xffffffffu, va.y, q);
        fb[P].x = __shfl_sync(0xffffffffu, vb.x, q);
        fb[P].y = __shfl_sync(0xffffffffu, vb.y, q);
        gather_factors<P + 1>(fa, fb, va, vb);
    }
}

// ================= 3-qubit register circuit =================
__device__ __forceinline__ float2 cmul3(float2 a, float2 b) {
    return make_float2(a.x * b.x - a.y * b.y, a.x * b.y + a.y * b.x);
}
__device__ __forceinline__ float2 cadd3(float2 a, float2 b) {
    return make_float2(a.x + b.x, a.y + b.y);
}
__device__ __forceinline__ void run3(float x0, float x1, float x2,
                                     const float2* __restrict__ M, float E[3]) {
    float c[3], s[3];
    __sincosf(0.5f * x0, &s[0], &c[0]);
    __sincosf(0.5f * x1, &s[1], &c[1]);
    __sincosf(0.5f * x2, &s[2], &c[2]);
    float2 a[8];
#pragma unroll
    for (int i = 0; i < 8; i++) {
        float v = ((i >> 2) & 1 ? s[0] : c[0]) *
                  ((i >> 1) & 1 ? s[1] : c[1]) *
                  ((i      ) & 1 ? s[2] : c[2]);
        a[i] = make_float2(v, 0.f);
    }
#pragma unroll
    for (int l = 0; l < 4; l++) {
#pragma unroll
        for (int w = 0; w < 3; w++) {
            const float2* m = M + (l * 3 + w) * 4;
            const int p = 2 - w;
#pragma unroll
            for (int i0 = 0; i0 < 8; i0++) {
                if (i0 & (1 << p)) continue;
                int i1 = i0 | (1 << p);
                float2 A = a[i0], B = a[i1];
                a[i0] = cadd3(cmul3(m[0], A), cmul3(m[1], B));
                a[i1] = cadd3(cmul3(m[2], A), cmul3(m[3], B));
            }
        }
        const int r = (l & 1) + 1;
#pragma unroll
        for (int i = 0; i < 3; i++) {
            int pc = 2 - i;
            int pt = 2 - ((i + r) % 3);
#pragma unroll
            for (int idx = 0; idx < 8; idx++) {
                if (((idx >> pc) & 1) && !((idx >> pt) & 1)) {
                    int j = idx | (1 << pt);
                    float2 t = a[idx]; a[idx] = a[j]; a[j] = t;
                }
            }
        }
    }
    E[0] = E[1] = E[2] = 0.f;
#pragma unroll
    for (int i = 0; i < 8; i++) {
        float p = a[i].x * a[i].x + a[i].y * a[i].y;
        E[0] += (i & 4) ? -p : p;
        E[1] += (i & 2) ? -p : p;
        E[2] += (i & 1) ? -p : p;
    }
}

// ================= prep: Rot matrices (precise, off critical path) ==========
__global__ void prep_kernel(const float* __restrict__ t_stem,
                            const float* __restrict__ t_attn,
                            const float* __restrict__ t_ffn,
                            const float* __restrict__ t_red) {
    int i = blockIdx.x * blockDim.x + threadIdx.x;
    if (i < 960) {
        const float* a;
        if (i < 120)      a = t_stem + i * 3;
        else if (i < 600) a = t_attn + (i - 120) * 3;
        else if (i < 840) a = t_ffn  + (i - 600) * 3;
        else              a = t_red  + (i - 840) * 3;
        float phi = a[0], th = a[1], om = a[2];
        float c, s, cp, sp, cm, sm;
        sincosf(0.5f * th, &s, &c);
        sincosf(0.5f * (phi + om), &sp, &cp);
        sincosf(0.5f * (phi - om), &sm, &cm);
        float2* m = &g_mats[i * 4];
        m[0] = make_float2( cp * c, -sp * c);
        m[1] = make_float2(-cm * s, -sm * s);
        m[2] = make_float2( cm * s, -sm * s);
        m[3] = make_float2( cp * c,  sp * c);
    }
}

// ================= stem =================
__global__ void stem_kernel(const float* __restrict__ x) {
    int i = blockIdx.x * blockDim.x + threadIdx.x;
    int t = i >> 10, b = i & 1023;
    float E[3];
    run3(x[b * 30 + 3 * t], x[b * 30 + 3 * t + 1], x[b * 30 + 3 * t + 2],
         g_mats + (t * 12) * 4, E);
#pragma unroll
    for (int k = 0; k < 3; k++) g_H[b * 30 + 3 * t + k] = E[k];
}

// ================= attention: warp-resident 10-qubit simulator =================
__global__ void __launch_bounds__(128) attn_kernel(int lay) {
    const int wid  = blockIdx.x * 4 + (threadIdx.x >> 5);
    const int lane = threadIdx.x & 31;
    const int b  = wid & 1023;
    const int hg = wid >> 10;
    const int h  = hg / 3, g = hg % 3;
    const float2* gm = g_mats + (120 + ((lay * 2 + h) * 3 + g) * 40) * 4;

    // ---- init: product state of V_q|0>, V_q = Rot(layer0,q) * RY(x_q) ----
    float2 va, vb;
    {
        int q = (lane < NT) ? lane : 0;
        float ang = (lane < NT) ? g_H[b * 30 + 3 * lane + g] : 0.f;
        float c, s;
        __sincosf(0.5f * ang, &s, &c);
        float2 g00 = gm[q * 4 + 0];
        float2 g01 = gm[q * 4 + 1];
        va = make_float2( g00.x * c + g01.x * s,  g00.y * c + g01.y * s);
        vb = make_float2(-g01.x * c + g00.x * s,  g01.y * c - g00.y * s);
    }
    float2 fa[NT], fb[NT];
    gather_factors<0>(fa, fb, va, vb);
    // lane-bit factor (positions 5..9)
    float2 lf = (lane & 1) ? fb[5] : fa[5];
#pragma unroll
    for (int p = 6; p < NT; p++)
        lf = cmulf(lf, ((lane >> (p - 5)) & 1) ? fb[p] : fa[p]);
    // local doubling table (positions 0..4)
    float2 T[32];
    T[0] = cmulf(lf, fa[0]);
    T[1] = cmulf(lf, fb[0]);
#pragma unroll
    for (int k = 1; k < 5; k++) {
#pragma unroll
        for (int j = 0; j < 16; j++) {
            if (j < (1 << k)) {
                T[j | (1 << k)] = cmulf(T[j], fb[k]);
                T[j]            = cmulf(T[j], fa[k]);
            }
        }
    }
    u64 st[32];
#pragma unroll
    for (int j = 0; j < 32; j++) st[j] = pack2(T[j].x, T[j].y);

    // ---- layers 1..3 (conjugated gates, compile-time masks) ----
    run_gates<0>(st, gm, lane);

    // ---- measurement ----
    float pr[32];
#pragma unroll
    for (int j = 0; j < 32; j++) {
        float2 f = unpack2(st[j]);
        pr[j] = f.x * f.x + f.y * f.y;
    }
    float res[NT];
    meas_from<0>(pr, res, lane);
#pragma unroll
    for (int w = 0; w < NT; w++) {
#pragma unroll
        for (int off = 16; off; off >>= 1)
            res[w] += __shfl_xor_sync(0xffffffffu, res[w], off);
    }
    if (lane == 0) {
#pragma unroll
        for (int w = 0; w < NT; w++)
            g_attn[b * 60 + h * 30 + 3 * w + g] = res[w];
    }
}

// ================= fused W_O projection + residual + FFN =================
__global__ void wo_ffn_kernel(const float* __restrict__ W_O, int lay) {
    int gt = blockIdx.x * blockDim.x + threadIdx.x;
    int b = gt >> 5, lane = gt & 31;

    float newH = 0.f;
    if (lane < 30) {
        const float4* wrow = (const float4*)(W_O + (lay * 30 + lane) * 60);
        const float4* arow = (const float4*)(g_attn + b * 60);
        float s0 = 0.f, s1 = 0.f, s2 = 0.f, s3 = 0.f;
#pragma unroll
        for (int k = 0; k < 15; k++) {
            float4 w4 = wrow[k];
            float4 a4 = arow[k];
            s0 = fmaf(a4.x, w4.x, s0);
            s1 = fmaf(a4.y, w4.y, s1);
            s2 = fmaf(a4.z, w4.z, s2);
            s3 = fmaf(a4.w, w4.w, s3);
        }
        newH = g_H[b * 30 + lane] + ((s0 + s1) + (s2 + s3));
    }
    __syncwarp();

    // FFN input shuffle: feature f = 3*lane + j needs H[3*(f%10) + f/10]
    int f0 = 3 * lane, f1 = f0 + 1, f2 = f0 + 2;
    float in0 = __shfl_sync(0xffffffffu, newH, (3 * (f0 % 10) + f0 / 10) & 31);
    float in1 = __shfl_sync(0xffffffffu, newH, (3 * (f1 % 10) + f1 / 10) & 31);
    float in2 = __shfl_sync(0xffffffffu, newH, (3 * (f2 % 10) + f2 / 10) & 31);
    if (lane >= 10) { in0 = 0.f; in1 = 0.f; in2 = 0.f; }
    int t = (lane < 10) ? lane : 0;
    float E[3];
    run3(in0, in1, in2, g_mats + (600 + (lay * 10 + t) * 12) * 4, E);

    float h0 = __shfl_sync(0xffffffffu, newH, (3 * lane) & 31);
    float h1 = __shfl_sync(0xffffffffu, newH, (3 * lane + 1) & 31);
    float h2 = __shfl_sync(0xffffffffu, newH, (3 * lane + 2) & 31);
    if (lane < 10) {
        g_H[b * 30 + 3 * lane + 0] = h0 + E[0];
        g_H[b * 30 + 3 * lane + 1] = h1 + E[1];
        g_H[b * 30 + 3 * lane + 2] = h2 + E[2];
    }
}

// ================= reduce + classification =================
__global__ void reduce_cls_kernel(const float* __restrict__ Wc,
                                  const float* __restrict__ bc,
                                  float* __restrict__ out) {
    int gt = blockIdx.x * blockDim.x + threadIdx.x;
    int b = gt >> 5, lane = gt & 31;
    float red = 0.f;
    if (lane < 10) {
        float E[3];
        run3(g_H[b * 30 + 3 * lane], g_H[b * 30 + 3 * lane + 1], g_H[b * 30 + 3 * lane + 2],
             g_mats + (840 + lane * 12) * 4, E);
        red = E[0];
    }
    float rv[10];
#pragma unroll
    for (int t = 0; t < 10; t++)
        rv[t] = __shfl_sync(0xffffffffu, red, t);
    if (lane < 10) {
        float s = bc[lane];
#pragma unroll
        for (int t = 0; t < 10; t++) s += rv[t] * Wc[lane * 10 + t];
        out[b * 10 + lane] = s;
    }
}

// ================= launch =================
extern "C" void kernel_launch(void* const* d_in, const int* in_sizes, int n_in,
                              void* d_out, int out_size) {
    const float* x_      = (const float*)d_in[0];
    const float* t_stem  = (const float*)d_in[1];
    const float* t_attn  = (const float*)d_in[2];
    const float* W_O     = (const float*)d_in[3];
    const float* t_ffn   = (const float*)d_in[4];
    const float* t_red   = (const float*)d_in[5];
    const float* W_cls   = (const float*)d_in[6];
    const float* b_cls   = (const float*)d_in[7];
    float* out = (float*)d_out;

    prep_kernel<<<4, 256>>>(t_stem, t_attn, t_ffn, t_red);
    stem_kernel<<<40, 256>>>(x_);
    for (int l = 0; l < LAYERS; l++) {
        attn_kernel<<<1536, 128>>>(l);
        wo_ffn_kernel<<<128, 256>>>(W_O, l);
    }
    reduce_cls_kernel<<<128, 256>>>(W_cls, b_cls, out);
}